// round 13
// baseline (speedup 1.0000x reference)
#include <cuda_runtime.h>
#include <cuda_bf16.h>
#include <cuda_fp16.h>
#include <stdint.h>
#include <math.h>

// Problem constants (fixed by the reference)
#define NN 100000
#define NE 1600000
static constexpr int KDIM = 128;
static constexpr int HID  = 128;
static constexpr int OUTD = 64;
static constexpr int NB_SCAN = (NN + 1023) / 1024;

// ---------------- device scratch ---------------------------------------------
__device__ float  g_deg [NN];
__device__ float  g_dinv[NN];
__device__ int    g_rowptr[NN];
__device__ int    g_cursor[NN];
__device__ int    g_part[128];
__device__ int    g_eidx[NE];
__device__ __half g_h1  [(size_t)NN * HID];    // fp16 features (layer-1 GEMM out)
__device__ __half g_h2  [(size_t)NN * OUTD];   // fp16 features (layer-2 GEMM out)

// ---------------- degree / normalization -------------------------------------
__global__ void k_init_deg() {
    int i = blockIdx.x * blockDim.x + threadIdx.x;
    if (i < NN) g_deg[i] = 1.0f;
}
__global__ void k_deg(const int* __restrict__ tgt) {
    int e = blockIdx.x * blockDim.x + threadIdx.x;
    if (e < NE) atomicAdd(&g_deg[tgt[e]], 1.0f);
}

// ---------------- CSR build (scan fused with dinv) ----------------------------
__global__ void k_scan_block() {
    __shared__ int sd[256];
    int tid  = threadIdx.x;
    int base = blockIdx.x * 1024 + tid * 4;
    int v[4], s = 0;
#pragma unroll
    for (int j = 0; j < 4; j++) {
        int i = base + j;
        int c = 0;
        if (i < NN) {
            float d = g_deg[i];
            g_dinv[i] = rsqrtf(d);
            c = (int)d - 1;
        }
        v[j] = s; s += c;
    }
    sd[tid] = s; __syncthreads();
    for (int off = 1; off < 256; off <<= 1) {
        int t = (tid >= off) ? sd[tid - off] : 0;
        __syncthreads(); sd[tid] += t; __syncthreads();
    }
    int excl = sd[tid] - s;
#pragma unroll
    for (int j = 0; j < 4; j++) {
        int i = base + j;
        if (i < NN) g_rowptr[i] = excl + v[j];
    }
    if (tid == 255) g_part[blockIdx.x] = sd[255];
}

__global__ void k_scan_spine() {
    __shared__ int sp[128];
    int tid = threadIdx.x;
    int v = (tid < NB_SCAN) ? g_part[tid] : 0;
    sp[tid] = v; __syncthreads();
    for (int off = 1; off < 128; off <<= 1) {
        int t = (tid >= off) ? sp[tid - off] : 0;
        __syncthreads(); sp[tid] += t; __syncthreads();
    }
    g_part[tid] = sp[tid] - v;
}

__global__ void k_scan_add() {
    int i = blockIdx.x * blockDim.x + threadIdx.x;
    if (i < NN) {
        g_rowptr[i] += g_part[i >> 10];
        g_cursor[i] = 0;
    }
}

__global__ void k_fill(const int* __restrict__ src, const int* __restrict__ tgt) {
    int e = blockIdx.x * blockDim.x + threadIdx.x;
    if (e >= NE) return;
    int t = tgt[e];
    int pos = g_rowptr[t] + atomicAdd(&g_cursor[t], 1);
    g_eidx[pos] = src[e];
}

// ---------------- bf16 / fp16 helpers -----------------------------------------
__device__ __forceinline__ unsigned pk_bf16x2(float lo, float hi) {
    unsigned r;
    asm("cvt.rn.bf16x2.f32 %0, %1, %2;" : "=r"(r) : "f"(hi), "f"(lo));
    return r;
}
__device__ __forceinline__ float bf16_round(float x) {
    return __bfloat162float(__float2bfloat16_rn(x));
}
__device__ __forceinline__ float4 up4(uint2 r) {
    float2 fa = __half22float2(*(__half2*)&r.x);
    float2 fb = __half22float2(*(__half2*)&r.y);
    return make_float4(fa.x, fa.y, fb.x, fb.y);
}

#define MMA_BF16(c, a, b)                                                     \
    asm volatile(                                                             \
        "mma.sync.aligned.m16n8k16.row.col.f32.bf16.bf16.f32 "                \
        "{%0,%1,%2,%3}, {%4,%5,%6,%7}, {%8,%9}, {%0,%1,%2,%3};"               \
        : "+f"((c)[0]), "+f"((c)[1]), "+f"((c)[2]), "+f"((c)[3])              \
        : "r"((a)[0]), "r"((a)[1]), "r"((a)[2]), "r"((a)[3]),                 \
          "r"((b)[0]), "r"((b)[1]))

static constexpr int KS = KDIM + 8;   // 136 bf16 elems per smem row
static constexpr int KW = KS / 2;     // 68 words per row

// ---------------- GEMM1: 3x-bf16-split, fp32 input, fp16 output ---------------
__global__ void __launch_bounds__(512)
k_gemm1(const float* __restrict__ A, const float* __restrict__ W,
        __half* __restrict__ H) {
    constexpr int BM = 256, BN = 128, WMC = 4, MF = 4, NF = 4;

    extern __shared__ char smc[];
    unsigned* ah32 = (unsigned*)smc;
    unsigned* al32 = ah32 + BM * KW;
    unsigned* wh32 = al32 + BM * KW;
    unsigned* wl32 = wh32 + BN * KW;

    const int tid  = threadIdx.x;
    const int row0 = blockIdx.x * BM;

    for (int i = tid; i < (KDIM / 4) * BN; i += 512) {
        int n  = i % BN;
        int kb = (i / BN) * 4;
        float f0 = W[(kb + 0) * BN + n];
        float f1 = W[(kb + 1) * BN + n];
        float f2 = W[(kb + 2) * BN + n];
        float f3 = W[(kb + 3) * BN + n];
        float h0 = bf16_round(f0), h1 = bf16_round(f1);
        float h2 = bf16_round(f2), h3 = bf16_round(f3);
        int wi = (n * KW + kb / 2) >> 1;
        ((uint2*)wh32)[wi] = make_uint2(pk_bf16x2(h0, h1), pk_bf16x2(h2, h3));
        ((uint2*)wl32)[wi] = make_uint2(pk_bf16x2(f0 - h0, f1 - h1),
                                        pk_bf16x2(f2 - h2, f3 - h3));
    }
    for (int i = tid * 4; i < BM * KDIM; i += 512 * 4) {
        int r = i / KDIM, c = i % KDIM;
        int gr = row0 + r;
        float4 v = make_float4(0.f, 0.f, 0.f, 0.f);
        if (gr < NN) v = *(const float4*)(A + (size_t)gr * KDIM + c);
        float h0 = bf16_round(v.x), h1 = bf16_round(v.y);
        float h2 = bf16_round(v.z), h3 = bf16_round(v.w);
        int wi = (r * KW + c / 2) >> 1;
        ((uint2*)ah32)[wi] = make_uint2(pk_bf16x2(h0, h1), pk_bf16x2(h2, h3));
        ((uint2*)al32)[wi] = make_uint2(pk_bf16x2(v.x - h0, v.y - h1),
                                        pk_bf16x2(v.z - h2, v.w - h3));
    }
    __syncthreads();

    const int w    = tid >> 5, lane = tid & 31;
    const int wm   = w % WMC,  wn   = w / WMC;
    const int m0   = wm * (MF * 16), n0 = wn * (NF * 8);
    const int grp  = lane >> 2, q   = lane & 3;

    float acc[MF][NF][4];
#pragma unroll
    for (int i = 0; i < MF; i++)
#pragma unroll
        for (int j = 0; j < NF; j++)
#pragma unroll
            for (int t = 0; t < 4; t++) acc[i][j][t] = 0.f;

#pragma unroll 2
    for (int k0 = 0; k0 < KDIM; k0 += 16) {
        const int kw = (k0 >> 1) + q;
        unsigned ah[MF][4], al[MF][4];
#pragma unroll
        for (int mf = 0; mf < MF; mf++) {
            int m = m0 + mf * 16 + grp;
            ah[mf][0] = ah32[m * KW + kw];
            ah[mf][1] = ah32[(m + 8) * KW + kw];
            ah[mf][2] = ah32[m * KW + kw + 4];
            ah[mf][3] = ah32[(m + 8) * KW + kw + 4];
            al[mf][0] = al32[m * KW + kw];
            al[mf][1] = al32[(m + 8) * KW + kw];
            al[mf][2] = al32[m * KW + kw + 4];
            al[mf][3] = al32[(m + 8) * KW + kw + 4];
        }
        unsigned bh[NF][2], bl[NF][2];
#pragma unroll
        for (int nf = 0; nf < NF; nf++) {
            int n = n0 + nf * 8 + grp;
            bh[nf][0] = wh32[n * KW + kw];
            bh[nf][1] = wh32[n * KW + kw + 4];
            bl[nf][0] = wl32[n * KW + kw];
            bl[nf][1] = wl32[n * KW + kw + 4];
        }
#pragma unroll
        for (int mf = 0; mf < MF; mf++)
#pragma unroll
            for (int nf = 0; nf < NF; nf++) {
                MMA_BF16(acc[mf][nf], ah[mf], bh[nf]);
                MMA_BF16(acc[mf][nf], ah[mf], bl[nf]);
                MMA_BF16(acc[mf][nf], al[mf], bh[nf]);
            }
    }

#pragma unroll
    for (int mf = 0; mf < MF; mf++) {
        int r1 = row0 + m0 + mf * 16 + grp;
        int r2 = r1 + 8;
#pragma unroll
        for (int nf = 0; nf < NF; nf++) {
            int col = n0 + nf * 8 + 2 * q;
            if (r1 < NN)
                *(__half2*)(H + (size_t)r1 * BN + col) =
                    __floats2half2_rn(acc[mf][nf][0], acc[mf][nf][1]);
            if (r2 < NN)
                *(__half2*)(H + (size_t)r2 * BN + col) =
                    __floats2half2_rn(acc[mf][nf][2], acc[mf][nf][3]);
        }
    }
}

// ---------------- FUSED: agg1 (gather h1) + GEMM2 -----------------------------
// Phase 1: each warp aggregates 16 nodes of relu(agg1+b1) and writes the bf16
//          hi/lo split DIRECTLY into the GEMM A smem planes (no gmem round-trip).
// Phase 2: GEMM2 mainloop (BN=64), fp16 output h2.
__global__ void __launch_bounds__(512)
k_agg1_gemm2(const __half* __restrict__ h1, const float* __restrict__ b1,
             const float* __restrict__ W, __half* __restrict__ H) {
    constexpr int BM = 256, BN = 64, WMC = 8, MF = 2, NF = 4;

    extern __shared__ char smc[];
    unsigned* ah32 = (unsigned*)smc;
    unsigned* al32 = ah32 + BM * KW;
    unsigned* wh32 = al32 + BM * KW;
    unsigned* wl32 = wh32 + BN * KW;

    const int tid  = threadIdx.x;
    const int w    = tid >> 5, lane = tid & 31;
    const int row0 = blockIdx.x * BM;

    // stage W transposed + split
    for (int i = tid; i < (KDIM / 4) * BN; i += 512) {
        int n  = i % BN;
        int kb = (i / BN) * 4;
        float f0 = W[(kb + 0) * BN + n];
        float f1 = W[(kb + 1) * BN + n];
        float f2 = W[(kb + 2) * BN + n];
        float f3 = W[(kb + 3) * BN + n];
        float h0 = bf16_round(f0), h1v = bf16_round(f1);
        float h2 = bf16_round(f2), h3 = bf16_round(f3);
        int wi = (n * KW + kb / 2) >> 1;
        ((uint2*)wh32)[wi] = make_uint2(pk_bf16x2(h0, h1v), pk_bf16x2(h2, h3));
        ((uint2*)wl32)[wi] = make_uint2(pk_bf16x2(f0 - h0, f1 - h1v),
                                        pk_bf16x2(f2 - h2, f3 - h3));
    }

    // Phase 1: gather + aggregate 16 nodes per warp; split into A planes.
    const uint2* hp = (const uint2*)h1;
    const float4 bb = ((const float4*)b1)[lane];
#pragma unroll 1
    for (int j = 0; j < 16; j++) {
        int r  = w * 16 + j;                       // local row
        int gn = row0 + r;
        float4 acc = make_float4(0.f, 0.f, 0.f, 0.f);
        if (gn < NN) {
            const float dt  = g_dinv[gn];
            const int   beg = g_rowptr[gn];
            const int   end = beg + ((int)g_deg[gn] - 1);
            acc = up4(hp[(size_t)gn * 32 + lane]);
            float ws = dt * dt;
            acc.x *= ws; acc.y *= ws; acc.z *= ws; acc.w *= ws;
            int e = beg;
            for (; e + 4 <= end; e += 4) {
                int s0 = g_eidx[e],     s1 = g_eidx[e + 1];
                int s2 = g_eidx[e + 2], s3 = g_eidx[e + 3];
                float w0 = dt * g_dinv[s0], w1 = dt * g_dinv[s1];
                float w2 = dt * g_dinv[s2], w3 = dt * g_dinv[s3];
                float4 v0 = up4(hp[(size_t)s0 * 32 + lane]);
                float4 v1 = up4(hp[(size_t)s1 * 32 + lane]);
                float4 v2 = up4(hp[(size_t)s2 * 32 + lane]);
                float4 v3 = up4(hp[(size_t)s3 * 32 + lane]);
                acc.x += w0 * v0.x + w1 * v1.x + w2 * v2.x + w3 * v3.x;
                acc.y += w0 * v0.y + w1 * v1.y + w2 * v2.y + w3 * v3.y;
                acc.z += w0 * v0.z + w1 * v1.z + w2 * v2.z + w3 * v3.z;
                acc.w += w0 * v0.w + w1 * v1.w + w2 * v2.w + w3 * v3.w;
            }
            for (; e < end; e++) {
                int s = g_eidx[e];
                float wv = dt * g_dinv[s];
                float4 v = up4(hp[(size_t)s * 32 + lane]);
                acc.x += wv * v.x; acc.y += wv * v.y;
                acc.z += wv * v.z; acc.w += wv * v.w;
            }
            acc.x = fmaxf(acc.x + bb.x, 0.f);
            acc.y = fmaxf(acc.y + bb.y, 0.f);
            acc.z = fmaxf(acc.z + bb.z, 0.f);
            acc.w = fmaxf(acc.w + bb.w, 0.f);
        }
        float h0 = bf16_round(acc.x), h1v = bf16_round(acc.y);
        float h2 = bf16_round(acc.z), h3 = bf16_round(acc.w);
        ((uint2*)ah32)[r * (KW / 2) + lane] =
            make_uint2(pk_bf16x2(h0, h1v), pk_bf16x2(h2, h3));
        ((uint2*)al32)[r * (KW / 2) + lane] =
            make_uint2(pk_bf16x2(acc.x - h0, acc.y - h1v),
                       pk_bf16x2(acc.z - h2, acc.w - h3));
    }
    __syncthreads();

    // Phase 2: GEMM2 mainloop
    const int wm  = w % WMC, wn = w / WMC;
    const int m0  = wm * (MF * 16), n0 = wn * (NF * 8);
    const int grp = lane >> 2, q = lane & 3;

    float acc[MF][NF][4];
#pragma unroll
    for (int i = 0; i < MF; i++)
#pragma unroll
        for (int j = 0; j < NF; j++)
#pragma unroll
            for (int t = 0; t < 4; t++) acc[i][j][t] = 0.f;

#pragma unroll 2
    for (int k0 = 0; k0 < KDIM; k0 += 16) {
        const int kw = (k0 >> 1) + q;
        unsigned ah[MF][4], al[MF][4];
#pragma unroll
        for (int mf = 0; mf < MF; mf++) {
            int m = m0 + mf * 16 + grp;
            ah[mf][0] = ah32[m * KW + kw];
            ah[mf][1] = ah32[(m + 8) * KW + kw];
            ah[mf][2] = ah32[m * KW + kw + 4];
            ah[mf][3] = ah32[(m + 8) * KW + kw + 4];
            al[mf][0] = al32[m * KW + kw];
            al[mf][1] = al32[(m + 8) * KW + kw];
            al[mf][2] = al32[m * KW + kw + 4];
            al[mf][3] = al32[(m + 8) * KW + kw + 4];
        }
        unsigned bh[NF][2], bl[NF][2];
#pragma unroll
        for (int nf = 0; nf < NF; nf++) {
            int n = n0 + nf * 8 + grp;
            bh[nf][0] = wh32[n * KW + kw];
            bh[nf][1] = wh32[n * KW + kw + 4];
            bl[nf][0] = wl32[n * KW + kw];
            bl[nf][1] = wl32[n * KW + kw + 4];
        }
#pragma unroll
        for (int mf = 0; mf < MF; mf++)
#pragma unroll
            for (int nf = 0; nf < NF; nf++) {
                MMA_BF16(acc[mf][nf], ah[mf], bh[nf]);
                MMA_BF16(acc[mf][nf], ah[mf], bl[nf]);
                MMA_BF16(acc[mf][nf], al[mf], bh[nf]);
            }
    }

#pragma unroll
    for (int mf = 0; mf < MF; mf++) {
        int r1 = row0 + m0 + mf * 16 + grp;
        int r2 = r1 + 8;
#pragma unroll
        for (int nf = 0; nf < NF; nf++) {
            int col = n0 + nf * 8 + 2 * q;
            if (r1 < NN)
                *(__half2*)(H + (size_t)r1 * BN + col) =
                    __floats2half2_rn(acc[mf][nf][0], acc[mf][nf][1]);
            if (r2 < NN)
                *(__half2*)(H + (size_t)r2 * BN + col) =
                    __floats2half2_rn(acc[mf][nf][2], acc[mf][nf][3]);
        }
    }
}

// ---------------- agg2: warp per node, D=64, fp32 output + b2 -----------------
__global__ void __launch_bounds__(256)
k_agg2(const __half* __restrict__ h, float* __restrict__ out,
       const float* __restrict__ bias) {
    int gw   = (blockIdx.x * 256 + threadIdx.x) >> 5;
    int lane = threadIdx.x & 31;
    if (gw >= NN) return;
    const float dt  = g_dinv[gw];
    const int   beg = g_rowptr[gw];
    const int   end = beg + ((int)g_deg[gw] - 1);
    const uint2* hp = (const uint2*)h;

    const int c    = lane & 15;                // 16 uint2 chunks = full row
    const int half = lane >> 4;
    float4 acc = make_float4(0.f, 0.f, 0.f, 0.f);
    if (half == 0) {
        acc = up4(hp[(size_t)gw * 16 + c]);
        float ws = dt * dt;
        acc.x *= ws; acc.y *= ws; acc.z *= ws; acc.w *= ws;
        float4 b = ((const float4*)bias)[c];
        acc.x += b.x; acc.y += b.y; acc.z += b.z; acc.w += b.w;
    }
    int e = beg + half;
    for (; e + 4 <= end; e += 4) {             // 2 per half-warp -> 4 in flight
        int s0 = g_eidx[e], s1 = g_eidx[e + 2];
        float w0 = dt * g_dinv[s0], w1 = dt * g_dinv[s1];
        float4 v0 = up4(hp[(size_t)s0 * 16 + c]);
        float4 v1 = up4(hp[(size_t)s1 * 16 + c]);
        acc.x += w0 * v0.x + w1 * v1.x;
        acc.y += w0 * v0.y + w1 * v1.y;
        acc.z += w0 * v0.z + w1 * v1.z;
        acc.w += w0 * v0.w + w1 * v1.w;
    }
    for (; e < end; e += 2) {
        int s = g_eidx[e];
        float wv = dt * g_dinv[s];
        float4 v = up4(hp[(size_t)s * 16 + c]);
        acc.x += wv * v.x; acc.y += wv * v.y;
        acc.z += wv * v.z; acc.w += wv * v.w;
    }
    acc.x += __shfl_down_sync(0xffffffffu, acc.x, 16);
    acc.y += __shfl_down_sync(0xffffffffu, acc.y, 16);
    acc.z += __shfl_down_sync(0xffffffffu, acc.z, 16);
    acc.w += __shfl_down_sync(0xffffffffu, acc.w, 16);
    if (half == 0) ((float4*)out)[(size_t)gw * 16 + c] = acc;
}

// ---------------- launcher ----------------------------------------------------
extern "C" void kernel_launch(void* const* d_in, const int* in_sizes, int n_in,
                              void* d_out, int out_size) {
    const float* x  = (const float*)d_in[0];
    const int*   ei = (const int*)  d_in[1];
    const float* W1 = (const float*)d_in[2];
    const float* b1 = (const float*)d_in[3];
    const float* W2 = (const float*)d_in[4];
    const float* b2 = (const float*)d_in[5];
    float* out = (float*)d_out;

    const int* src = ei;
    const int* tgt = ei + NE;

    void *p_h1, *p_h2;
    cudaGetSymbolAddress(&p_h1, g_h1);
    cudaGetSymbolAddress(&p_h2, g_h2);
    __half* h1 = (__half*)p_h1;
    __half* h2 = (__half*)p_h2;

    const int smem1 = (2 * 256 * KW + 2 * 128 * KW) * 4;     // 208896 B
    const int smem2 = (2 * 256 * KW + 2 * 64  * KW) * 4;     // 174080 B
    cudaFuncSetAttribute((const void*)k_gemm1,
                         cudaFuncAttributeMaxDynamicSharedMemorySize, smem1);
    cudaFuncSetAttribute((const void*)k_agg1_gemm2,
                         cudaFuncAttributeMaxDynamicSharedMemorySize, smem2);

    static cudaStream_t s_csr = nullptr;
    static cudaEvent_t  ev_fork = nullptr, ev_join = nullptr;
    if (!s_csr) {
        cudaStreamCreateWithFlags(&s_csr, cudaStreamNonBlocking);
        cudaEventCreateWithFlags(&ev_fork, cudaEventDisableTiming);
        cudaEventCreateWithFlags(&ev_join, cudaEventDisableTiming);
    }

    // fork: CSR build runs concurrently with GEMM1
    cudaEventRecord(ev_fork, 0);
    cudaStreamWaitEvent(s_csr, ev_fork, 0);
    k_init_deg  <<<(NN + 255) / 256, 256, 0, s_csr>>>();
    k_deg       <<<(NE + 255) / 256, 256, 0, s_csr>>>(tgt);
    k_scan_block<<<NB_SCAN, 256, 0, s_csr>>>();
    k_scan_spine<<<1, 128, 0, s_csr>>>();
    k_scan_add  <<<(NN + 255) / 256, 256, 0, s_csr>>>();
    k_fill      <<<(NE + 255) / 256, 256, 0, s_csr>>>(src, tgt);
    cudaEventRecord(ev_join, s_csr);

    // GEMM1 on main stream (independent of CSR)
    k_gemm1<<<(NN + 255) / 256, 512, smem1>>>(x, W1, h1);

    // join, then fused agg1+GEMM2, then agg2 -> out
    cudaStreamWaitEvent(0, ev_join, 0);
    k_agg1_gemm2<<<(NN + 255) / 256, 512, smem2>>>(h1, b1, W2, h2);
    k_agg2<<<(NN * 32 + 255) / 256, 256>>>(h2, out, b2);
}

// round 15
// speedup vs baseline: 1.2030x; 1.2030x over previous
#include <cuda_runtime.h>
#include <cuda_bf16.h>
#include <cuda_fp16.h>
#include <stdint.h>
#include <math.h>

// Problem constants (fixed by the reference)
#define NN 100000
#define NE 1600000
static constexpr int KDIM = 128;
static constexpr int HID  = 128;
static constexpr int OUTD = 64;
static constexpr int NB_SCAN = (NN + 1023) / 1024;

// ---------------- device scratch ---------------------------------------------
__device__ float  g_deg [NN];
__device__ float  g_dinv[NN];
__device__ int    g_rowptr[NN];
__device__ int    g_cursor[NN];
__device__ int    g_part[128];
__device__ int    g_eidx[NE];
__device__ __half g_h1  [(size_t)NN * HID];    // fp16 features (layer-1 GEMM out)
__device__ __half g_a1h [(size_t)NN * HID];    // fp16 relu(agg1+b1) (GEMM2 input)
__device__ __half g_h2  [(size_t)NN * OUTD];

// ---------------- degree / normalization -------------------------------------
__global__ void k_init_deg() {
    int i = blockIdx.x * blockDim.x + threadIdx.x;
    if (i < NN) g_deg[i] = 1.0f;
}
__global__ void k_deg(const int* __restrict__ tgt) {
    int e = blockIdx.x * blockDim.x + threadIdx.x;
    if (e < NE) atomicAdd(&g_deg[tgt[e]], 1.0f);
}

// ---------------- CSR build (scan fused with dinv) ----------------------------
__global__ void k_scan_block() {
    __shared__ int sd[256];
    int tid  = threadIdx.x;
    int base = blockIdx.x * 1024 + tid * 4;
    int v[4], s = 0;
#pragma unroll
    for (int j = 0; j < 4; j++) {
        int i = base + j;
        int c = 0;
        if (i < NN) {
            float d = g_deg[i];
            g_dinv[i] = rsqrtf(d);
            c = (int)d - 1;
        }
        v[j] = s; s += c;
    }
    sd[tid] = s; __syncthreads();
    for (int off = 1; off < 256; off <<= 1) {
        int t = (tid >= off) ? sd[tid - off] : 0;
        __syncthreads(); sd[tid] += t; __syncthreads();
    }
    int excl = sd[tid] - s;
#pragma unroll
    for (int j = 0; j < 4; j++) {
        int i = base + j;
        if (i < NN) g_rowptr[i] = excl + v[j];
    }
    if (tid == 255) g_part[blockIdx.x] = sd[255];
}

__global__ void k_scan_spine() {
    __shared__ int sp[128];
    int tid = threadIdx.x;
    int v = (tid < NB_SCAN) ? g_part[tid] : 0;
    sp[tid] = v; __syncthreads();
    for (int off = 1; off < 128; off <<= 1) {
        int t = (tid >= off) ? sp[tid - off] : 0;
        __syncthreads(); sp[tid] += t; __syncthreads();
    }
    g_part[tid] = sp[tid] - v;
}

__global__ void k_scan_add() {
    int i = blockIdx.x * blockDim.x + threadIdx.x;
    if (i < NN) {
        g_rowptr[i] += g_part[i >> 10];
        g_cursor[i] = 0;
    }
}

__global__ void k_fill(const int* __restrict__ src, const int* __restrict__ tgt) {
    int e = blockIdx.x * blockDim.x + threadIdx.x;
    if (e >= NE) return;
    int t = tgt[e];
    int pos = g_rowptr[t] + atomicAdd(&g_cursor[t], 1);
    g_eidx[pos] = src[e];
}

// ---------------- bf16 / fp16 helpers -----------------------------------------
__device__ __forceinline__ unsigned pk_bf16x2(float lo, float hi) {
    unsigned r;
    asm("cvt.rn.bf16x2.f32 %0, %1, %2;" : "=r"(r) : "f"(hi), "f"(lo));
    return r;
}
__device__ __forceinline__ float bf16_round(float x) {
    return __bfloat162float(__float2bfloat16_rn(x));
}
__device__ __forceinline__ float4 up4(uint2 r) {
    float2 fa = __half22float2(*(__half2*)&r.x);
    float2 fb = __half22float2(*(__half2*)&r.y);
    return make_float4(fa.x, fa.y, fb.x, fb.y);
}
__device__ __forceinline__ uint32_t smem_u32(const void* p) {
    return (uint32_t)__cvta_generic_to_shared(p);
}

#define MMA_BF16(c, a, b)                                                     \
    asm volatile(                                                             \
        "mma.sync.aligned.m16n8k16.row.col.f32.bf16.bf16.f32 "                \
        "{%0,%1,%2,%3}, {%4,%5,%6,%7}, {%8,%9}, {%0,%1,%2,%3};"               \
        : "+f"((c)[0]), "+f"((c)[1]), "+f"((c)[2]), "+f"((c)[3])              \
        : "r"((a)[0]), "r"((a)[1]), "r"((a)[2]), "r"((a)[3]),                 \
          "r"((b)[0]), "r"((b)[1]))

#define LDSM_X4(r0, r1, r2, r3, addr)                                         \
    asm volatile(                                                             \
        "ldmatrix.sync.aligned.m8n8.x4.shared.b16 {%0,%1,%2,%3}, [%4];"       \
        : "=r"(r0), "=r"(r1), "=r"(r2), "=r"(r3) : "r"(addr))

static constexpr int KS = KDIM + 8;   // 136 bf16 elems per smem row
static constexpr int KW = KS / 2;     // 68 words per row

// ---------------- 3x-bf16-split tensor-core GEMM (ldmatrix frag loads) --------
// CTA 512 thr, tile 256 x BN. A and W pre-split into bf16 hi/lo planes in smem.
// AT = float (layer 1 input) or __half (layer 2 input). NF must be 4.
template<int BN, int WMC, int MF, int NF, typename AT>
__global__ void __launch_bounds__(512)
k_gemm_bf(const AT* __restrict__ A, const float* __restrict__ W,
          __half* __restrict__ H) {
    constexpr int BM = 256;
    static_assert(NF == 4, "B ldmatrix path assumes NF==4");

    extern __shared__ char smc[];
    unsigned* ah32 = (unsigned*)smc;
    unsigned* al32 = ah32 + BM * KW;
    unsigned* wh32 = al32 + BM * KW;
    unsigned* wl32 = wh32 + BN * KW;

    const int tid  = threadIdx.x;
    const int row0 = blockIdx.x * BM;

    // stage W transposed + split
    for (int i = tid; i < (KDIM / 4) * BN; i += 512) {
        int n  = i % BN;
        int kb = (i / BN) * 4;
        float f0 = W[(kb + 0) * BN + n];
        float f1 = W[(kb + 1) * BN + n];
        float f2 = W[(kb + 2) * BN + n];
        float f3 = W[(kb + 3) * BN + n];
        float h0 = bf16_round(f0), h1 = bf16_round(f1);
        float h2 = bf16_round(f2), h3 = bf16_round(f3);
        int wi = (n * KW + kb / 2) >> 1;
        ((uint2*)wh32)[wi] = make_uint2(pk_bf16x2(h0, h1), pk_bf16x2(h2, h3));
        ((uint2*)wl32)[wi] = make_uint2(pk_bf16x2(f0 - h0, f1 - h1),
                                        pk_bf16x2(f2 - h2, f3 - h3));
    }
    // stage A + split
    for (int i = tid * 4; i < BM * KDIM; i += 512 * 4) {
        int r = i / KDIM, c = i % KDIM;
        int gr = row0 + r;
        float4 v = make_float4(0.f, 0.f, 0.f, 0.f);
        if (gr < NN) {
            if (sizeof(AT) == 4) {
                v = *(const float4*)((const float*)A + (size_t)gr * KDIM + c);
            } else {
                v = up4(*(const uint2*)((const __half*)A + (size_t)gr * KDIM + c));
            }
        }
        float h0 = bf16_round(v.x), h1 = bf16_round(v.y);
        float h2 = bf16_round(v.z), h3 = bf16_round(v.w);
        int wi = (r * KW + c / 2) >> 1;
        ((uint2*)ah32)[wi] = make_uint2(pk_bf16x2(h0, h1), pk_bf16x2(h2, h3));
        ((uint2*)al32)[wi] = make_uint2(pk_bf16x2(v.x - h0, v.y - h1),
                                        pk_bf16x2(v.z - h2, v.w - h3));
    }
    __syncthreads();

    const int w    = tid >> 5, lane = tid & 31;
    const int wm   = w % WMC,  wn   = w / WMC;
    const int m0   = wm * (MF * 16), n0 = wn * (NF * 8);
    const int grp  = lane >> 2, q   = lane & 3;

    // ldmatrix per-lane source rows
    // A tiles (x4): g0 rows m..m+7 kLo, g1 m+8.. kLo, g2 m.. kHi, g3 m+8.. kHi
    const int rlA = lane & 15;
    const int ksA = (lane >> 4) * 4;                 // word offset for k-half
    // B tiles (x4): g0 n..n+7 kLo, g1 n.. kHi, g2 n+8.. kLo, g3 n+8.. kHi
    const int rlB = (lane & 7) + ((lane >> 4) << 3);
    const int ksB = ((lane >> 3) & 1) * 4;

    const uint32_t ahB = smem_u32(ah32), alB = smem_u32(al32);
    const uint32_t whB = smem_u32(wh32), wlB = smem_u32(wl32);

    uint32_t offAh[MF], offAl[MF];
#pragma unroll
    for (int mf = 0; mf < MF; mf++) {
        uint32_t o = (uint32_t)(((m0 + mf * 16 + rlA) * KW + ksA) * 4);
        offAh[mf] = ahB + o; offAl[mf] = alB + o;
    }
    uint32_t offBh[2], offBl[2];
#pragma unroll
    for (int p = 0; p < 2; p++) {
        uint32_t o = (uint32_t)(((n0 + p * 16 + rlB) * KW + ksB) * 4);
        offBh[p] = whB + o; offBl[p] = wlB + o;
    }

    float acc[MF][NF][4];
#pragma unroll
    for (int i = 0; i < MF; i++)
#pragma unroll
        for (int j = 0; j < NF; j++)
#pragma unroll
            for (int t = 0; t < 4; t++) acc[i][j][t] = 0.f;

#pragma unroll 2
    for (int k0 = 0; k0 < KDIM; k0 += 16) {
        const uint32_t kb = (uint32_t)(k0 * 2);      // byte shift: (k0/2)*4
        unsigned ah[MF][4], al[MF][4];
#pragma unroll
        for (int mf = 0; mf < MF; mf++) {
            LDSM_X4(ah[mf][0], ah[mf][1], ah[mf][2], ah[mf][3], offAh[mf] + kb);
            LDSM_X4(al[mf][0], al[mf][1], al[mf][2], al[mf][3], offAl[mf] + kb);
        }
        unsigned bh[2][4], bl[2][4];                 // [pair][nfLow k0,k1, nfHigh k0,k1]
#pragma unroll
        for (int p = 0; p < 2; p++) {
            LDSM_X4(bh[p][0], bh[p][1], bh[p][2], bh[p][3], offBh[p] + kb);
            LDSM_X4(bl[p][0], bl[p][1], bl[p][2], bl[p][3], offBl[p] + kb);
        }
#pragma unroll
        for (int mf = 0; mf < MF; mf++)
#pragma unroll
            for (int nf = 0; nf < NF; nf++) {
                unsigned* bhf = &bh[nf >> 1][(nf & 1) * 2];
                unsigned* blf = &bl[nf >> 1][(nf & 1) * 2];
                MMA_BF16(acc[mf][nf], ah[mf], bhf);
                MMA_BF16(acc[mf][nf], ah[mf], blf);
                MMA_BF16(acc[mf][nf], al[mf], bhf);
            }
    }

#pragma unroll
    for (int mf = 0; mf < MF; mf++) {
        int r1 = row0 + m0 + mf * 16 + grp;
        int r2 = r1 + 8;
#pragma unroll
        for (int nf = 0; nf < NF; nf++) {
            int col = n0 + nf * 8 + 2 * q;
            if (r1 < NN)
                *(__half2*)(H + (size_t)r1 * BN + col) =
                    __floats2half2_rn(acc[mf][nf][0], acc[mf][nf][1]);
            if (r2 < NN)
                *(__half2*)(H + (size_t)r2 * BN + col) =
                    __floats2half2_rn(acc[mf][nf][2], acc[mf][nf][3]);
        }
    }
}

// ---------------- CSR aggregation: warp per target node, fp16 gather ----------
// Layer 1 (D=128, RELUB): out_h = fp16(relu(agg + b[col]))
// Layer 2 (D=64,  !RELUB): out_f = agg + b[col]   (fp32 d_out)
template<int D, bool RELUB>
__global__ void __launch_bounds__(256)
k_agg(const __half* __restrict__ h, __half* __restrict__ out_h,
      float* __restrict__ out_f, const float* __restrict__ bias) {
    int gw   = (blockIdx.x * 256 + threadIdx.x) >> 5;
    int lane = threadIdx.x & 31;
    if (gw >= NN) return;
    const float dt  = g_dinv[gw];
    const int   beg = g_rowptr[gw];
    const int   end = beg + ((int)g_deg[gw] - 1);
    const uint2* hp = (const uint2*)h;

    if (D == 128) {
        const int c = lane;                       // 32 uint2 chunks = full row
        float4 acc = up4(hp[(size_t)gw * 32 + c]);
        float ws = dt * dt;
        acc.x *= ws; acc.y *= ws; acc.z *= ws; acc.w *= ws;
        int e = beg;
        for (; e + 8 <= end; e += 8) {            // 8 edges in flight
            int   s[8]; float wv[8]; float4 v[8];
#pragma unroll
            for (int j = 0; j < 8; j++) s[j] = g_eidx[e + j];
#pragma unroll
            for (int j = 0; j < 8; j++) wv[j] = dt * g_dinv[s[j]];
#pragma unroll
            for (int j = 0; j < 8; j++) v[j] = up4(hp[(size_t)s[j] * 32 + c]);
#pragma unroll
            for (int j = 0; j < 8; j++) {
                acc.x += wv[j] * v[j].x; acc.y += wv[j] * v[j].y;
                acc.z += wv[j] * v[j].z; acc.w += wv[j] * v[j].w;
            }
        }
        for (; e + 4 <= end; e += 4) {
            int s0 = g_eidx[e],     s1 = g_eidx[e + 1];
            int s2 = g_eidx[e + 2], s3 = g_eidx[e + 3];
            float w0 = dt * g_dinv[s0], w1 = dt * g_dinv[s1];
            float w2 = dt * g_dinv[s2], w3 = dt * g_dinv[s3];
            float4 v0 = up4(hp[(size_t)s0 * 32 + c]);
            float4 v1 = up4(hp[(size_t)s1 * 32 + c]);
            float4 v2 = up4(hp[(size_t)s2 * 32 + c]);
            float4 v3 = up4(hp[(size_t)s3 * 32 + c]);
            acc.x += w0 * v0.x + w1 * v1.x + w2 * v2.x + w3 * v3.x;
            acc.y += w0 * v0.y + w1 * v1.y + w2 * v2.y + w3 * v3.y;
            acc.z += w0 * v0.z + w1 * v1.z + w2 * v2.z + w3 * v3.z;
            acc.w += w0 * v0.w + w1 * v1.w + w2 * v2.w + w3 * v3.w;
        }
        for (; e < end; e++) {
            int s = g_eidx[e];
            float wv = dt * g_dinv[s];
            float4 v = up4(hp[(size_t)s * 32 + c]);
            acc.x += wv * v.x; acc.y += wv * v.y;
            acc.z += wv * v.z; acc.w += wv * v.w;
        }
        if (RELUB) {
            float4 b = ((const float4*)bias)[c];
            acc.x = fmaxf(acc.x + b.x, 0.f);
            acc.y = fmaxf(acc.y + b.y, 0.f);
            acc.z = fmaxf(acc.z + b.z, 0.f);
            acc.w = fmaxf(acc.w + b.w, 0.f);
            __half2 p0 = __floats2half2_rn(acc.x, acc.y);
            __half2 p1 = __floats2half2_rn(acc.z, acc.w);
            ((uint2*)out_h)[(size_t)gw * 32 + c] =
                make_uint2(*(uint32_t*)&p0, *(uint32_t*)&p1);
        } else {
            ((float4*)out_f)[(size_t)gw * 32 + c] = acc;
        }
    } else {                                      // D=64: 16 chunks, 2 edges per half
        const int c    = lane & 15;
        const int half = lane >> 4;
        float4 acc = make_float4(0.f, 0.f, 0.f, 0.f);
        if (half == 0) {
            acc = up4(hp[(size_t)gw * 16 + c]);
            float ws = dt * dt;
            acc.x *= ws; acc.y *= ws; acc.z *= ws; acc.w *= ws;
            float4 b = ((const float4*)bias)[c];
            acc.x += b.x; acc.y += b.y; acc.z += b.z; acc.w += b.w;
        }
        int e = beg + half;
        for (; e + 4 <= end; e += 4) {            // 2 per half-warp -> 4 in flight
            int s0 = g_eidx[e], s1 = g_eidx[e + 2];
            float w0 = dt * g_dinv[s0], w1 = dt * g_dinv[s1];
            float4 v0 = up4(hp[(size_t)s0 * 16 + c]);
            float4 v1 = up4(hp[(size_t)s1 * 16 + c]);
            acc.x += w0 * v0.x + w1 * v1.x;
            acc.y += w0 * v0.y + w1 * v1.y;
            acc.z += w0 * v0.z + w1 * v1.z;
            acc.w += w0 * v0.w + w1 * v1.w;
        }
        for (; e < end; e += 2) {
            int s = g_eidx[e];
            float wv = dt * g_dinv[s];
            float4 v = up4(hp[(size_t)s * 16 + c]);
            acc.x += wv * v.x; acc.y += wv * v.y;
            acc.z += wv * v.z; acc.w += wv * v.w;
        }
        acc.x += __shfl_down_sync(0xffffffffu, acc.x, 16);
        acc.y += __shfl_down_sync(0xffffffffu, acc.y, 16);
        acc.z += __shfl_down_sync(0xffffffffu, acc.z, 16);
        acc.w += __shfl_down_sync(0xffffffffu, acc.w, 16);
        if (half == 0) ((float4*)out_f)[(size_t)gw * 16 + c] = acc;
    }
}

// ---------------- launcher ----------------------------------------------------
extern "C" void kernel_launch(void* const* d_in, const int* in_sizes, int n_in,
                              void* d_out, int out_size) {
    const float* x  = (const float*)d_in[0];
    const int*   ei = (const int*)  d_in[1];
    const float* W1 = (const float*)d_in[2];
    const float* b1 = (const float*)d_in[3];
    const float* W2 = (const float*)d_in[4];
    const float* b2 = (const float*)d_in[5];
    float* out = (float*)d_out;

    const int* src = ei;
    const int* tgt = ei + NE;

    void *p_h1, *p_a1h, *p_h2;
    cudaGetSymbolAddress(&p_h1,  g_h1);
    cudaGetSymbolAddress(&p_a1h, g_a1h);
    cudaGetSymbolAddress(&p_h2,  g_h2);
    __half* h1  = (__half*)p_h1;
    __half* a1h = (__half*)p_a1h;
    __half* h2  = (__half*)p_h2;

    const int smem1 = (2 * 256 * KW + 2 * 128 * KW) * 4;     // 208896 B
    const int smem2 = (2 * 256 * KW + 2 * 64  * KW) * 4;     // 174080 B
    cudaFuncSetAttribute((const void*)k_gemm_bf<128, 4, 4, 4, float>,
                         cudaFuncAttributeMaxDynamicSharedMemorySize, smem1);
    cudaFuncSetAttribute((const void*)k_gemm_bf<64, 8, 2, 4, __half>,
                         cudaFuncAttributeMaxDynamicSharedMemorySize, smem2);

    static cudaStream_t s_csr = nullptr;
    static cudaEvent_t  ev_fork = nullptr, ev_join = nullptr;
    if (!s_csr) {
        cudaStreamCreateWithFlags(&s_csr, cudaStreamNonBlocking);
        cudaEventCreateWithFlags(&ev_fork, cudaEventDisableTiming);
        cudaEventCreateWithFlags(&ev_join, cudaEventDisableTiming);
    }

    // fork: CSR build runs concurrently with GEMM1
    cudaEventRecord(ev_fork, 0);
    cudaStreamWaitEvent(s_csr, ev_fork, 0);
    k_init_deg  <<<(NN + 255) / 256, 256, 0, s_csr>>>();
    k_deg       <<<(NE + 255) / 256, 256, 0, s_csr>>>(tgt);
    k_scan_block<<<NB_SCAN, 256, 0, s_csr>>>();
    k_scan_spine<<<1, 128, 0, s_csr>>>();
    k_scan_add  <<<(NN + 255) / 256, 256, 0, s_csr>>>();
    k_fill      <<<(NE + 255) / 256, 256, 0, s_csr>>>(src, tgt);
    cudaEventRecord(ev_join, s_csr);

    // GEMM1 on main stream (independent of CSR)
    k_gemm_bf<128, 4, 4, 4, float><<<(NN + 255) / 256, 512, smem1>>>(x, W1, h1);

    // join, then: a1h = fp16(relu(agg(h1) + b1)) ; h2 = a1h @ W2 ; out = agg(h2) + b2
    cudaStreamWaitEvent(0, ev_join, 0);
    k_agg<128, true><<<(NN * 32 + 255) / 256, 256>>>(h1, a1h, nullptr, b1);
    k_gemm_bf<64, 8, 2, 4, __half><<<(NN + 255) / 256, 512, smem2>>>(a1h, W2, h2);
    k_agg<64, false><<<(NN * 32 + 255) / 256, 256>>>(h2, nullptr, out, b2);
}

// round 16
// speedup vs baseline: 1.2136x; 1.0088x over previous
#include <cuda_runtime.h>
#include <cuda_bf16.h>
#include <cuda_fp16.h>
#include <stdint.h>
#include <math.h>

// Problem constants (fixed by the reference)
#define NN 100000
#define NE 1600000
static constexpr int KDIM = 128;
static constexpr int HID  = 128;
static constexpr int OUTD = 64;
static constexpr int NB_SCAN = (NN + 1023) / 1024;
static constexpr int CH0_TILES = 196;                 // GEMM2 chunk-0 tiles
static constexpr int CH0_NODES = CH0_TILES * 256;     // 50176

// ---------------- device scratch ---------------------------------------------
__device__ int    g_cnt [NN];                 // in-edge counts (memset to 0)
__device__ float  g_dinv[NN];
__device__ int    g_rowptr[NN];
__device__ int    g_rowcur[NN];               // fill cursors (= rowptr copy)
__device__ int    g_part[128];
__device__ int2   g_edge[NE];                 // {src, bits(dinv[src])}
__device__ __half g_h1  [(size_t)NN * HID];
__device__ __half g_a1h [(size_t)NN * HID];
__device__ __half g_h2  [(size_t)NN * OUTD];

// ---------------- degree -------------------------------------------------------
__global__ void k_deg(const int* __restrict__ tgt) {
    int e = blockIdx.x * blockDim.x + threadIdx.x;
    if (e < NE) atomicAdd(&g_cnt[tgt[e]], 1);
}

// ---------------- CSR build (scan fused with dinv) ----------------------------
__global__ void k_scan_block() {
    __shared__ int sd[256];
    int tid  = threadIdx.x;
    int base = blockIdx.x * 1024 + tid * 4;
    int v[4], s = 0;
#pragma unroll
    for (int j = 0; j < 4; j++) {
        int i = base + j;
        int c = 0;
        if (i < NN) {
            c = g_cnt[i];
            g_dinv[i] = rsqrtf((float)(c + 1));   // +1 self-loop
        }
        v[j] = s; s += c;
    }
    sd[tid] = s; __syncthreads();
    for (int off = 1; off < 256; off <<= 1) {
        int t = (tid >= off) ? sd[tid - off] : 0;
        __syncthreads(); sd[tid] += t; __syncthreads();
    }
    int excl = sd[tid] - s;
#pragma unroll
    for (int j = 0; j < 4; j++) {
        int i = base + j;
        if (i < NN) g_rowptr[i] = excl + v[j];
    }
    if (tid == 255) g_part[blockIdx.x] = sd[255];
}

__global__ void k_scan_spine() {
    __shared__ int sp[128];
    int tid = threadIdx.x;
    int v = (tid < NB_SCAN) ? g_part[tid] : 0;
    sp[tid] = v; __syncthreads();
    for (int off = 1; off < 128; off <<= 1) {
        int t = (tid >= off) ? sp[tid - off] : 0;
        __syncthreads(); sp[tid] += t; __syncthreads();
    }
    g_part[tid] = sp[tid] - v;
}

__global__ void k_scan_add() {
    int i = blockIdx.x * blockDim.x + threadIdx.x;
    if (i < NN) {
        int rp = g_rowptr[i] + g_part[i >> 10];
        g_rowptr[i] = rp;
        g_rowcur[i] = rp;
    }
}

// fill edge list with {src, dinv[src]} — kills random dinv loads in the aggs
__global__ void k_fill(const int* __restrict__ src, const int* __restrict__ tgt) {
    int e = blockIdx.x * blockDim.x + threadIdx.x;
    if (e >= NE) return;
    int t = tgt[e];
    int s = src[e];
    int pos = atomicAdd(&g_rowcur[t], 1);
    g_edge[pos] = make_int2(s, __float_as_int(g_dinv[s]));
}

// ---------------- bf16 / fp16 helpers -----------------------------------------
__device__ __forceinline__ unsigned pk_bf16x2(float lo, float hi) {
    unsigned r;
    asm("cvt.rn.bf16x2.f32 %0, %1, %2;" : "=r"(r) : "f"(hi), "f"(lo));
    return r;
}
__device__ __forceinline__ float bf16_round(float x) {
    return __bfloat162float(__float2bfloat16_rn(x));
}
__device__ __forceinline__ float4 up4(uint2 r) {
    float2 fa = __half22float2(*(__half2*)&r.x);
    float2 fb = __half22float2(*(__half2*)&r.y);
    return make_float4(fa.x, fa.y, fb.x, fb.y);
}
__device__ __forceinline__ uint32_t smem_u32(const void* p) {
    return (uint32_t)__cvta_generic_to_shared(p);
}

#define MMA_BF16(c, a, b)                                                     \
    asm volatile(                                                             \
        "mma.sync.aligned.m16n8k16.row.col.f32.bf16.bf16.f32 "                \
        "{%0,%1,%2,%3}, {%4,%5,%6,%7}, {%8,%9}, {%0,%1,%2,%3};"               \
        : "+f"((c)[0]), "+f"((c)[1]), "+f"((c)[2]), "+f"((c)[3])              \
        : "r"((a)[0]), "r"((a)[1]), "r"((a)[2]), "r"((a)[3]),                 \
          "r"((b)[0]), "r"((b)[1]))

#define LDSM_X4(r0, r1, r2, r3, addr)                                         \
    asm volatile(                                                             \
        "ldmatrix.sync.aligned.m8n8.x4.shared.b16 {%0,%1,%2,%3}, [%4];"       \
        : "=r"(r0), "=r"(r1), "=r"(r2), "=r"(r3) : "r"(addr))

static constexpr int KS = KDIM + 8;   // 136 bf16 elems per smem row
static constexpr int KW = KS / 2;     // 68 words per row

// ---------------- 3x-bf16-split tensor-core GEMM (ldmatrix frag loads) --------
// CTA 512 thr, tile 256 x BN. tile0 = tile offset (chunked launches).
template<int BN, int WMC, int MF, int NF, typename AT>
__global__ void __launch_bounds__(512)
k_gemm_bf(const AT* __restrict__ A, const float* __restrict__ W,
          __half* __restrict__ H, int tile0) {
    constexpr int BM = 256;
    static_assert(NF == 4, "B ldmatrix path assumes NF==4");

    extern __shared__ char smc[];
    unsigned* ah32 = (unsigned*)smc;
    unsigned* al32 = ah32 + BM * KW;
    unsigned* wh32 = al32 + BM * KW;
    unsigned* wl32 = wh32 + BN * KW;

    const int tid  = threadIdx.x;
    const int row0 = (tile0 + blockIdx.x) * BM;

    // stage W transposed + split
    for (int i = tid; i < (KDIM / 4) * BN; i += 512) {
        int n  = i % BN;
        int kb = (i / BN) * 4;
        float f0 = W[(kb + 0) * BN + n];
        float f1 = W[(kb + 1) * BN + n];
        float f2 = W[(kb + 2) * BN + n];
        float f3 = W[(kb + 3) * BN + n];
        float h0 = bf16_round(f0), h1 = bf16_round(f1);
        float h2 = bf16_round(f2), h3 = bf16_round(f3);
        int wi = (n * KW + kb / 2) >> 1;
        ((uint2*)wh32)[wi] = make_uint2(pk_bf16x2(h0, h1), pk_bf16x2(h2, h3));
        ((uint2*)wl32)[wi] = make_uint2(pk_bf16x2(f0 - h0, f1 - h1),
                                        pk_bf16x2(f2 - h2, f3 - h3));
    }
    // stage A + split
    for (int i = tid * 4; i < BM * KDIM; i += 512 * 4) {
        int r = i / KDIM, c = i % KDIM;
        int gr = row0 + r;
        float4 v = make_float4(0.f, 0.f, 0.f, 0.f);
        if (gr < NN) {
            if (sizeof(AT) == 4) {
                v = *(const float4*)((const float*)A + (size_t)gr * KDIM + c);
            } else {
                v = up4(*(const uint2*)((const __half*)A + (size_t)gr * KDIM + c));
            }
        }
        float h0 = bf16_round(v.x), h1 = bf16_round(v.y);
        float h2 = bf16_round(v.z), h3 = bf16_round(v.w);
        int wi = (r * KW + c / 2) >> 1;
        ((uint2*)ah32)[wi] = make_uint2(pk_bf16x2(h0, h1), pk_bf16x2(h2, h3));
        ((uint2*)al32)[wi] = make_uint2(pk_bf16x2(v.x - h0, v.y - h1),
                                        pk_bf16x2(v.z - h2, v.w - h3));
    }
    __syncthreads();

    const int w    = tid >> 5, lane = tid & 31;
    const int wm   = w % WMC,  wn   = w / WMC;
    const int m0   = wm * (MF * 16), n0 = wn * (NF * 8);
    const int grp  = lane >> 2, q   = lane & 3;

    const int rlA = lane & 15;
    const int ksA = (lane >> 4) * 4;
    const int rlB = (lane & 7) + ((lane >> 4) << 3);
    const int ksB = ((lane >> 3) & 1) * 4;

    const uint32_t ahB = smem_u32(ah32), alB = smem_u32(al32);
    const uint32_t whB = smem_u32(wh32), wlB = smem_u32(wl32);

    uint32_t offAh[MF], offAl[MF];
#pragma unroll
    for (int mf = 0; mf < MF; mf++) {
        uint32_t o = (uint32_t)(((m0 + mf * 16 + rlA) * KW + ksA) * 4);
        offAh[mf] = ahB + o; offAl[mf] = alB + o;
    }
    uint32_t offBh[2], offBl[2];
#pragma unroll
    for (int p = 0; p < 2; p++) {
        uint32_t o = (uint32_t)(((n0 + p * 16 + rlB) * KW + ksB) * 4);
        offBh[p] = whB + o; offBl[p] = wlB + o;
    }

    float acc[MF][NF][4];
#pragma unroll
    for (int i = 0; i < MF; i++)
#pragma unroll
        for (int j = 0; j < NF; j++)
#pragma unroll
            for (int t = 0; t < 4; t++) acc[i][j][t] = 0.f;

#pragma unroll 2
    for (int k0 = 0; k0 < KDIM; k0 += 16) {
        const uint32_t kb = (uint32_t)(k0 * 2);
        unsigned ah[MF][4], al[MF][4];
#pragma unroll
        for (int mf = 0; mf < MF; mf++) {
            LDSM_X4(ah[mf][0], ah[mf][1], ah[mf][2], ah[mf][3], offAh[mf] + kb);
            LDSM_X4(al[mf][0], al[mf][1], al[mf][2], al[mf][3], offAl[mf] + kb);
        }
        unsigned bh[2][4], bl[2][4];
#pragma unroll
        for (int p = 0; p < 2; p++) {
            LDSM_X4(bh[p][0], bh[p][1], bh[p][2], bh[p][3], offBh[p] + kb);
            LDSM_X4(bl[p][0], bl[p][1], bl[p][2], bl[p][3], offBl[p] + kb);
        }
#pragma unroll
        for (int mf = 0; mf < MF; mf++)
#pragma unroll
            for (int nf = 0; nf < NF; nf++) {
                unsigned* bhf = &bh[nf >> 1][(nf & 1) * 2];
                unsigned* blf = &bl[nf >> 1][(nf & 1) * 2];
                MMA_BF16(acc[mf][nf], ah[mf], bhf);
                MMA_BF16(acc[mf][nf], ah[mf], blf);
                MMA_BF16(acc[mf][nf], al[mf], bhf);
            }
    }

#pragma unroll
    for (int mf = 0; mf < MF; mf++) {
        int r1 = row0 + m0 + mf * 16 + grp;
        int r2 = r1 + 8;
#pragma unroll
        for (int nf = 0; nf < NF; nf++) {
            int col = n0 + nf * 8 + 2 * q;
            if (r1 < NN)
                *(__half2*)(H + (size_t)r1 * BN + col) =
                    __floats2half2_rn(acc[mf][nf][0], acc[mf][nf][1]);
            if (r2 < NN)
                *(__half2*)(H + (size_t)r2 * BN + col) =
                    __floats2half2_rn(acc[mf][nf][2], acc[mf][nf][3]);
        }
    }
}

// ---------------- CSR aggregation: warp per target node, packed edges ---------
// edge = {src, bits(dinv[src])} -> no random dinv loads in the hot loop.
// Layer 1 (D=128, RELUB): out_h = fp16(relu(agg + b[col]))
// Layer 2 (D=64,  !RELUB): out_f = agg + b[col]
template<int D, bool RELUB>
__global__ void __launch_bounds__(256)
k_agg(const __half* __restrict__ h, __half* __restrict__ out_h,
      float* __restrict__ out_f, const float* __restrict__ bias,
      int nbase, int ncap) {
    int gw   = nbase + ((blockIdx.x * 256 + threadIdx.x) >> 5);
    int lane = threadIdx.x & 31;
    if (gw >= ncap) return;
    const float dt  = g_dinv[gw];
    const int   beg = g_rowptr[gw];
    const int   end = beg + g_cnt[gw];
    const uint2* hp = (const uint2*)h;

    if (D == 128) {
        const int c = lane;
        float4 acc = up4(hp[(size_t)gw * 32 + c]);
        float ws = dt * dt;
        acc.x *= ws; acc.y *= ws; acc.z *= ws; acc.w *= ws;
        int e = beg;
        for (; e + 8 <= end; e += 8) {
            int2 ed[8]; float4 v[8];
#pragma unroll
            for (int j = 0; j < 8; j++) ed[j] = g_edge[e + j];
#pragma unroll
            for (int j = 0; j < 8; j++) v[j] = up4(hp[(size_t)ed[j].x * 32 + c]);
#pragma unroll
            for (int j = 0; j < 8; j++) {
                float wv = dt * __int_as_float(ed[j].y);
                acc.x += wv * v[j].x; acc.y += wv * v[j].y;
                acc.z += wv * v[j].z; acc.w += wv * v[j].w;
            }
        }
        for (; e < end; e++) {
            int2 ed = g_edge[e];
            float wv = dt * __int_as_float(ed.y);
            float4 v = up4(hp[(size_t)ed.x * 32 + c]);
            acc.x += wv * v.x; acc.y += wv * v.y;
            acc.z += wv * v.z; acc.w += wv * v.w;
        }
        if (RELUB) {
            float4 b = ((const float4*)bias)[c];
            acc.x = fmaxf(acc.x + b.x, 0.f);
            acc.y = fmaxf(acc.y + b.y, 0.f);
            acc.z = fmaxf(acc.z + b.z, 0.f);
            acc.w = fmaxf(acc.w + b.w, 0.f);
            __half2 p0 = __floats2half2_rn(acc.x, acc.y);
            __half2 p1 = __floats2half2_rn(acc.z, acc.w);
            ((uint2*)out_h)[(size_t)gw * 32 + c] =
                make_uint2(*(uint32_t*)&p0, *(uint32_t*)&p1);
        } else {
            ((float4*)out_f)[(size_t)gw * 32 + c] = acc;
        }
    } else {                                      // D=64: 16 chunks, 2 per half
        const int c    = lane & 15;
        const int half = lane >> 4;
        float4 acc = make_float4(0.f, 0.f, 0.f, 0.f);
        if (half == 0) {
            acc = up4(hp[(size_t)gw * 16 + c]);
            float ws = dt * dt;
            acc.x *= ws; acc.y *= ws; acc.z *= ws; acc.w *= ws;
            float4 b = ((const float4*)bias)[c];
            acc.x += b.x; acc.y += b.y; acc.z += b.z; acc.w += b.w;
        }
        int e = beg + half;
        for (; e + 4 <= end; e += 4) {
            int2 e0 = g_edge[e], e1 = g_edge[e + 2];
            float w0 = dt * __int_as_float(e0.y);
            float w1 = dt * __int_as_float(e1.y);
            float4 v0 = up4(hp[(size_t)e0.x * 16 + c]);
            float4 v1 = up4(hp[(size_t)e1.x * 16 + c]);
            acc.x += w0 * v0.x + w1 * v1.x;
            acc.y += w0 * v0.y + w1 * v1.y;
            acc.z += w0 * v0.z + w1 * v1.z;
            acc.w += w0 * v0.w + w1 * v1.w;
        }
        for (; e < end; e += 2) {
            int2 ed = g_edge[e];
            float wv = dt * __int_as_float(ed.y);
            float4 v = up4(hp[(size_t)ed.x * 16 + c]);
            acc.x += wv * v.x; acc.y += wv * v.y;
            acc.z += wv * v.z; acc.w += wv * v.w;
        }
        acc.x += __shfl_down_sync(0xffffffffu, acc.x, 16);
        acc.y += __shfl_down_sync(0xffffffffu, acc.y, 16);
        acc.z += __shfl_down_sync(0xffffffffu, acc.z, 16);
        acc.w += __shfl_down_sync(0xffffffffu, acc.w, 16);
        if (half == 0) ((float4*)out_f)[(size_t)gw * 16 + c] = acc;
    }
}

// ---------------- launcher ----------------------------------------------------
extern "C" void kernel_launch(void* const* d_in, const int* in_sizes, int n_in,
                              void* d_out, int out_size) {
    const float* x  = (const float*)d_in[0];
    const int*   ei = (const int*)  d_in[1];
    const float* W1 = (const float*)d_in[2];
    const float* b1 = (const float*)d_in[3];
    const float* W2 = (const float*)d_in[4];
    const float* b2 = (const float*)d_in[5];
    float* out = (float*)d_out;

    const int* src = ei;
    const int* tgt = ei + NE;

    void *p_h1, *p_a1h, *p_h2, *p_cnt;
    cudaGetSymbolAddress(&p_h1,  g_h1);
    cudaGetSymbolAddress(&p_a1h, g_a1h);
    cudaGetSymbolAddress(&p_h2,  g_h2);
    cudaGetSymbolAddress(&p_cnt, g_cnt);
    __half* h1  = (__half*)p_h1;
    __half* a1h = (__half*)p_a1h;
    __half* h2  = (__half*)p_h2;

    const int smem1 = (2 * 256 * KW + 2 * 128 * KW) * 4;     // 208896 B
    const int smem2 = (2 * 256 * KW + 2 * 64  * KW) * 4;     // 174080 B
    cudaFuncSetAttribute((const void*)k_gemm_bf<128, 4, 4, 4, float>,
                         cudaFuncAttributeMaxDynamicSharedMemorySize, smem1);
    cudaFuncSetAttribute((const void*)k_gemm_bf<64, 8, 2, 4, __half>,
                         cudaFuncAttributeMaxDynamicSharedMemorySize, smem2);

    static cudaStream_t s_csr = nullptr;
    static cudaEvent_t  ev_fork = nullptr, ev_join = nullptr,
                        ev_c0 = nullptr, ev_c1 = nullptr;
    if (!s_csr) {
        cudaStreamCreateWithFlags(&s_csr, cudaStreamNonBlocking);
        cudaEventCreateWithFlags(&ev_fork, cudaEventDisableTiming);
        cudaEventCreateWithFlags(&ev_join, cudaEventDisableTiming);
        cudaEventCreateWithFlags(&ev_c0, cudaEventDisableTiming);
        cudaEventCreateWithFlags(&ev_c1, cudaEventDisableTiming);
    }

    // fork: CSR build runs concurrently with GEMM1
    cudaEventRecord(ev_fork, 0);
    cudaStreamWaitEvent(s_csr, ev_fork, 0);
    cudaMemsetAsync(p_cnt, 0, NN * sizeof(int), s_csr);
    k_deg       <<<(NE + 255) / 256, 256, 0, s_csr>>>(tgt);
    k_scan_block<<<NB_SCAN, 256, 0, s_csr>>>();
    k_scan_spine<<<1, 128, 0, s_csr>>>();
    k_scan_add  <<<(NN + 255) / 256, 256, 0, s_csr>>>();
    k_fill      <<<(NE + 255) / 256, 256, 0, s_csr>>>(src, tgt);
    cudaEventRecord(ev_join, s_csr);

    // GEMM1 on main stream (independent of CSR)
    k_gemm_bf<128, 4, 4, 4, float><<<(NN + 255) / 256, 512, smem1>>>(x, W1, h1, 0);

    // join, then chunked pipeline: agg1_c0 ; [agg1_c1 || GEMM2_c0] ; GEMM2_c1 ; agg2
    cudaStreamWaitEvent(0, ev_join, 0);
    k_agg<128, true><<<(CH0_NODES * 32) / 256, 256>>>(h1, a1h, nullptr, b1,
                                                      0, CH0_NODES);
    cudaEventRecord(ev_c0, 0);

    cudaStreamWaitEvent(s_csr, ev_c0, 0);
    k_agg<128, true><<<((NN - CH0_NODES) * 32 + 255) / 256, 256, 0, s_csr>>>(
        h1, a1h, nullptr, b1, CH0_NODES, NN);
    cudaEventRecord(ev_c1, s_csr);

    k_gemm_bf<64, 8, 2, 4, __half><<<CH0_TILES, 512, smem2>>>(a1h, W2, h2, 0);
    cudaStreamWaitEvent(0, ev_c1, 0);
    k_gemm_bf<64, 8, 2, 4, __half><<<(NN + 255) / 256 - CH0_TILES, 512, smem2>>>(
        a1h, W2, h2, CH0_TILES);
    k_agg<64, false><<<(NN * 32 + 255) / 256, 256>>>(h2, nullptr, out, b2, 0, NN);
}

// round 17
// speedup vs baseline: 1.2252x; 1.0095x over previous
#include <cuda_runtime.h>
#include <cuda_bf16.h>
#include <cuda_fp16.h>
#include <stdint.h>
#include <math.h>

// Problem constants (fixed by the reference)
#define NN 100000
#define NE 1600000
static constexpr int KDIM = 128;
static constexpr int HID  = 128;
static constexpr int OUTD = 64;
static constexpr int CH0_TILES = 196;                 // GEMM2 chunk-0 tiles
static constexpr int CH0_NODES = CH0_TILES * 256;     // 50176

// ---------------- device scratch ---------------------------------------------
__device__ int    g_cnt [NN];                 // in-edge counts (memset to 0)
__device__ int    g_total;                    // segment allocation cursor
__device__ float  g_dinv[NN];
__device__ int    g_rowptr[NN];
__device__ int    g_rowcur[NN];
__device__ int2   g_edge[NE];                 // {src, bits(dinv[src])}
__device__ __half g_h1  [(size_t)NN * HID];
__device__ __half g_a1h [(size_t)NN * HID];
__device__ __half g_h2  [(size_t)NN * OUTD];

// ---------------- degree -------------------------------------------------------
__global__ void k_deg(const int* __restrict__ tgt) {
    int e = blockIdx.x * blockDim.x + threadIdx.x;
    if (e == 0) g_total = 0;                  // safe: consumed by next kernel
    if (e < NE) atomicAdd(&g_cnt[tgt[e]], 1);
}

// ---------------- segment allocation (replaces 3-kernel prefix scan) ----------
// Order of segments is arbitrary (atomic arrival order) — aggregation is a sum,
// so only disjoint contiguous segments matter, not their order.
__global__ void k_alloc() {
    int i = blockIdx.x * blockDim.x + threadIdx.x;
    if (i >= NN) return;
    int c = g_cnt[i];
    g_dinv[i] = rsqrtf((float)(c + 1));       // +1 self-loop
    int rp = atomicAdd(&g_total, c);          // warp-aggregated by ptxas
    g_rowptr[i] = rp;
    g_rowcur[i] = rp;
}

// fill edge list with {src, dinv[src]} — kills random dinv loads in the aggs
__global__ void k_fill(const int* __restrict__ src, const int* __restrict__ tgt) {
    int e = blockIdx.x * blockDim.x + threadIdx.x;
    if (e >= NE) return;
    int t = tgt[e];
    int s = src[e];
    int pos = atomicAdd(&g_rowcur[t], 1);
    g_edge[pos] = make_int2(s, __float_as_int(g_dinv[s]));
}

// ---------------- bf16 / fp16 helpers -----------------------------------------
__device__ __forceinline__ unsigned pk_bf16x2(float lo, float hi) {
    unsigned r;
    asm("cvt.rn.bf16x2.f32 %0, %1, %2;" : "=r"(r) : "f"(hi), "f"(lo));
    return r;
}
__device__ __forceinline__ float bf16_round(float x) {
    return __bfloat162float(__float2bfloat16_rn(x));
}
__device__ __forceinline__ float4 up4(uint2 r) {
    float2 fa = __half22float2(*(__half2*)&r.x);
    float2 fb = __half22float2(*(__half2*)&r.y);
    return make_float4(fa.x, fa.y, fb.x, fb.y);
}
__device__ __forceinline__ uint32_t smem_u32(const void* p) {
    return (uint32_t)__cvta_generic_to_shared(p);
}

#define MMA_BF16(c, a, b)                                                     \
    asm volatile(                                                             \
        "mma.sync.aligned.m16n8k16.row.col.f32.bf16.bf16.f32 "                \
        "{%0,%1,%2,%3}, {%4,%5,%6,%7}, {%8,%9}, {%0,%1,%2,%3};"               \
        : "+f"((c)[0]), "+f"((c)[1]), "+f"((c)[2]), "+f"((c)[3])              \
        : "r"((a)[0]), "r"((a)[1]), "r"((a)[2]), "r"((a)[3]),                 \
          "r"((b)[0]), "r"((b)[1]))

#define LDSM_X4(r0, r1, r2, r3, addr)                                         \
    asm volatile(                                                             \
        "ldmatrix.sync.aligned.m8n8.x4.shared.b16 {%0,%1,%2,%3}, [%4];"       \
        : "=r"(r0), "=r"(r1), "=r"(r2), "=r"(r3) : "r"(addr))

static constexpr int KS = KDIM + 8;   // 136 bf16 elems per smem row
static constexpr int KW = KS / 2;     // 68 words per row

// ---------------- 3x-bf16-split tensor-core GEMM (ldmatrix frag loads) --------
// CTA 512 thr, tile 256 x BN. tile0 = tile offset (chunked launches).
template<int BN, int WMC, int MF, int NF, typename AT>
__global__ void __launch_bounds__(512)
k_gemm_bf(const AT* __restrict__ A, const float* __restrict__ W,
          __half* __restrict__ H, int tile0) {
    constexpr int BM = 256;
    static_assert(NF == 4, "B ldmatrix path assumes NF==4");

    extern __shared__ char smc[];
    unsigned* ah32 = (unsigned*)smc;
    unsigned* al32 = ah32 + BM * KW;
    unsigned* wh32 = al32 + BM * KW;
    unsigned* wl32 = wh32 + BN * KW;

    const int tid  = threadIdx.x;
    const int row0 = (tile0 + blockIdx.x) * BM;

    // stage W transposed + split
    for (int i = tid; i < (KDIM / 4) * BN; i += 512) {
        int n  = i % BN;
        int kb = (i / BN) * 4;
        float f0 = W[(kb + 0) * BN + n];
        float f1 = W[(kb + 1) * BN + n];
        float f2 = W[(kb + 2) * BN + n];
        float f3 = W[(kb + 3) * BN + n];
        float h0 = bf16_round(f0), h1 = bf16_round(f1);
        float h2 = bf16_round(f2), h3 = bf16_round(f3);
        int wi = (n * KW + kb / 2) >> 1;
        ((uint2*)wh32)[wi] = make_uint2(pk_bf16x2(h0, h1), pk_bf16x2(h2, h3));
        ((uint2*)wl32)[wi] = make_uint2(pk_bf16x2(f0 - h0, f1 - h1),
                                        pk_bf16x2(f2 - h2, f3 - h3));
    }
    // stage A + split
    for (int i = tid * 4; i < BM * KDIM; i += 512 * 4) {
        int r = i / KDIM, c = i % KDIM;
        int gr = row0 + r;
        float4 v = make_float4(0.f, 0.f, 0.f, 0.f);
        if (gr < NN) {
            if (sizeof(AT) == 4) {
                v = *(const float4*)((const float*)A + (size_t)gr * KDIM + c);
            } else {
                v = up4(*(const uint2*)((const __half*)A + (size_t)gr * KDIM + c));
            }
        }
        float h0 = bf16_round(v.x), h1 = bf16_round(v.y);
        float h2 = bf16_round(v.z), h3 = bf16_round(v.w);
        int wi = (r * KW + c / 2) >> 1;
        ((uint2*)ah32)[wi] = make_uint2(pk_bf16x2(h0, h1), pk_bf16x2(h2, h3));
        ((uint2*)al32)[wi] = make_uint2(pk_bf16x2(v.x - h0, v.y - h1),
                                        pk_bf16x2(v.z - h2, v.w - h3));
    }
    __syncthreads();

    const int w    = tid >> 5, lane = tid & 31;
    const int wm   = w % WMC,  wn   = w / WMC;
    const int m0   = wm * (MF * 16), n0 = wn * (NF * 8);
    const int grp  = lane >> 2, q   = lane & 3;

    const int rlA = lane & 15;
    const int ksA = (lane >> 4) * 4;
    const int rlB = (lane & 7) + ((lane >> 4) << 3);
    const int ksB = ((lane >> 3) & 1) * 4;

    const uint32_t ahB = smem_u32(ah32), alB = smem_u32(al32);
    const uint32_t whB = smem_u32(wh32), wlB = smem_u32(wl32);

    uint32_t offAh[MF], offAl[MF];
#pragma unroll
    for (int mf = 0; mf < MF; mf++) {
        uint32_t o = (uint32_t)(((m0 + mf * 16 + rlA) * KW + ksA) * 4);
        offAh[mf] = ahB + o; offAl[mf] = alB + o;
    }
    uint32_t offBh[2], offBl[2];
#pragma unroll
    for (int p = 0; p < 2; p++) {
        uint32_t o = (uint32_t)(((n0 + p * 16 + rlB) * KW + ksB) * 4);
        offBh[p] = whB + o; offBl[p] = wlB + o;
    }

    float acc[MF][NF][4];
#pragma unroll
    for (int i = 0; i < MF; i++)
#pragma unroll
        for (int j = 0; j < NF; j++)
#pragma unroll
            for (int t = 0; t < 4; t++) acc[i][j][t] = 0.f;

#pragma unroll 2
    for (int k0 = 0; k0 < KDIM; k0 += 16) {
        const uint32_t kb = (uint32_t)(k0 * 2);
        unsigned ah[MF][4], al[MF][4];
#pragma unroll
        for (int mf = 0; mf < MF; mf++) {
            LDSM_X4(ah[mf][0], ah[mf][1], ah[mf][2], ah[mf][3], offAh[mf] + kb);
            LDSM_X4(al[mf][0], al[mf][1], al[mf][2], al[mf][3], offAl[mf] + kb);
        }
        unsigned bh[2][4], bl[2][4];
#pragma unroll
        for (int p = 0; p < 2; p++) {
            LDSM_X4(bh[p][0], bh[p][1], bh[p][2], bh[p][3], offBh[p] + kb);
            LDSM_X4(bl[p][0], bl[p][1], bl[p][2], bl[p][3], offBl[p] + kb);
        }
#pragma unroll
        for (int mf = 0; mf < MF; mf++)
#pragma unroll
            for (int nf = 0; nf < NF; nf++) {
                unsigned* bhf = &bh[nf >> 1][(nf & 1) * 2];
                unsigned* blf = &bl[nf >> 1][(nf & 1) * 2];
                MMA_BF16(acc[mf][nf], ah[mf], bhf);
                MMA_BF16(acc[mf][nf], ah[mf], blf);
                MMA_BF16(acc[mf][nf], al[mf], bhf);
            }
    }

#pragma unroll
    for (int mf = 0; mf < MF; mf++) {
        int r1 = row0 + m0 + mf * 16 + grp;
        int r2 = r1 + 8;
#pragma unroll
        for (int nf = 0; nf < NF; nf++) {
            int col = n0 + nf * 8 + 2 * q;
            if (r1 < NN)
                *(__half2*)(H + (size_t)r1 * BN + col) =
                    __floats2half2_rn(acc[mf][nf][0], acc[mf][nf][1]);
            if (r2 < NN)
                *(__half2*)(H + (size_t)r2 * BN + col) =
                    __floats2half2_rn(acc[mf][nf][2], acc[mf][nf][3]);
        }
    }
}

// ---------------- CSR aggregation: warp per target node, packed edges ---------
// Layer 1 (D=128, RELUB): out_h = fp16(relu(agg + b[col]))
// Layer 2 (D=64,  !RELUB): out_f = agg + b[col]
template<int D, bool RELUB>
__global__ void __launch_bounds__(256)
k_agg(const __half* __restrict__ h, __half* __restrict__ out_h,
      float* __restrict__ out_f, const float* __restrict__ bias,
      int nbase, int ncap) {
    int gw   = nbase + ((blockIdx.x * 256 + threadIdx.x) >> 5);
    int lane = threadIdx.x & 31;
    if (gw >= ncap) return;
    const float dt  = g_dinv[gw];
    const int   beg = g_rowptr[gw];
    const int   end = beg + g_cnt[gw];
    const uint2* hp = (const uint2*)h;

    if (D == 128) {
        const int c = lane;
        float4 acc = up4(hp[(size_t)gw * 32 + c]);
        float ws = dt * dt;
        acc.x *= ws; acc.y *= ws; acc.z *= ws; acc.w *= ws;
        int e = beg;
        for (; e + 8 <= end; e += 8) {
            int2 ed[8]; float4 v[8];
#pragma unroll
            for (int j = 0; j < 8; j++) ed[j] = g_edge[e + j];
#pragma unroll
            for (int j = 0; j < 8; j++) v[j] = up4(hp[(size_t)ed[j].x * 32 + c]);
#pragma unroll
            for (int j = 0; j < 8; j++) {
                float wv = dt * __int_as_float(ed[j].y);
                acc.x += wv * v[j].x; acc.y += wv * v[j].y;
                acc.z += wv * v[j].z; acc.w += wv * v[j].w;
            }
        }
        for (; e < end; e++) {
            int2 ed = g_edge[e];
            float wv = dt * __int_as_float(ed.y);
            float4 v = up4(hp[(size_t)ed.x * 32 + c]);
            acc.x += wv * v.x; acc.y += wv * v.y;
            acc.z += wv * v.z; acc.w += wv * v.w;
        }
        if (RELUB) {
            float4 b = ((const float4*)bias)[c];
            acc.x = fmaxf(acc.x + b.x, 0.f);
            acc.y = fmaxf(acc.y + b.y, 0.f);
            acc.z = fmaxf(acc.z + b.z, 0.f);
            acc.w = fmaxf(acc.w + b.w, 0.f);
            __half2 p0 = __floats2half2_rn(acc.x, acc.y);
            __half2 p1 = __floats2half2_rn(acc.z, acc.w);
            ((uint2*)out_h)[(size_t)gw * 32 + c] =
                make_uint2(*(uint32_t*)&p0, *(uint32_t*)&p1);
        } else {
            ((float4*)out_f)[(size_t)gw * 32 + c] = acc;
        }
    } else {                                      // D=64: 16 chunks, 2 per half
        const int c    = lane & 15;
        const int half = lane >> 4;
        float4 acc = make_float4(0.f, 0.f, 0.f, 0.f);
        if (half == 0) {
            acc = up4(hp[(size_t)gw * 16 + c]);
            float ws = dt * dt;
            acc.x *= ws; acc.y *= ws; acc.z *= ws; acc.w *= ws;
            float4 b = ((const float4*)bias)[c];
            acc.x += b.x; acc.y += b.y; acc.z += b.z; acc.w += b.w;
        }
        int e = beg + half;
        for (; e + 4 <= end; e += 4) {
            int2 e0 = g_edge[e], e1 = g_edge[e + 2];
            float w0 = dt * __int_as_float(e0.y);
            float w1 = dt * __int_as_float(e1.y);
            float4 v0 = up4(hp[(size_t)e0.x * 16 + c]);
            float4 v1 = up4(hp[(size_t)e1.x * 16 + c]);
            acc.x += w0 * v0.x + w1 * v1.x;
            acc.y += w0 * v0.y + w1 * v1.y;
            acc.z += w0 * v0.z + w1 * v1.z;
            acc.w += w0 * v0.w + w1 * v1.w;
        }
        for (; e < end; e += 2) {
            int2 ed = g_edge[e];
            float wv = dt * __int_as_float(ed.y);
            float4 v = up4(hp[(size_t)ed.x * 16 + c]);
            acc.x += wv * v.x; acc.y += wv * v.y;
            acc.z += wv * v.z; acc.w += wv * v.w;
        }
        acc.x += __shfl_down_sync(0xffffffffu, acc.x, 16);
        acc.y += __shfl_down_sync(0xffffffffu, acc.y, 16);
        acc.z += __shfl_down_sync(0xffffffffu, acc.z, 16);
        acc.w += __shfl_down_sync(0xffffffffu, acc.w, 16);
        if (half == 0) ((float4*)out_f)[(size_t)gw * 16 + c] = acc;
    }
}

// ---------------- launcher ----------------------------------------------------
extern "C" void kernel_launch(void* const* d_in, const int* in_sizes, int n_in,
                              void* d_out, int out_size) {
    const float* x  = (const float*)d_in[0];
    const int*   ei = (const int*)  d_in[1];
    const float* W1 = (const float*)d_in[2];
    const float* b1 = (const float*)d_in[3];
    const float* W2 = (const float*)d_in[4];
    const float* b2 = (const float*)d_in[5];
    float* out = (float*)d_out;

    const int* src = ei;
    const int* tgt = ei + NE;

    void *p_h1, *p_a1h, *p_h2, *p_cnt;
    cudaGetSymbolAddress(&p_h1,  g_h1);
    cudaGetSymbolAddress(&p_a1h, g_a1h);
    cudaGetSymbolAddress(&p_h2,  g_h2);
    cudaGetSymbolAddress(&p_cnt, g_cnt);
    __half* h1  = (__half*)p_h1;
    __half* a1h = (__half*)p_a1h;
    __half* h2  = (__half*)p_h2;

    const int smem1 = (2 * 256 * KW + 2 * 128 * KW) * 4;     // 208896 B
    const int smem2 = (2 * 256 * KW + 2 * 64  * KW) * 4;     // 174080 B
    cudaFuncSetAttribute((const void*)k_gemm_bf<128, 4, 4, 4, float>,
                         cudaFuncAttributeMaxDynamicSharedMemorySize, smem1);
    cudaFuncSetAttribute((const void*)k_gemm_bf<64, 8, 2, 4, __half>,
                         cudaFuncAttributeMaxDynamicSharedMemorySize, smem2);

    static cudaStream_t s_csr = nullptr;
    static cudaEvent_t  ev_fork = nullptr, ev_join = nullptr,
                        ev_c0 = nullptr, ev_c1 = nullptr;
    if (!s_csr) {
        cudaStreamCreateWithFlags(&s_csr, cudaStreamNonBlocking);
        cudaEventCreateWithFlags(&ev_fork, cudaEventDisableTiming);
        cudaEventCreateWithFlags(&ev_join, cudaEventDisableTiming);
        cudaEventCreateWithFlags(&ev_c0, cudaEventDisableTiming);
        cudaEventCreateWithFlags(&ev_c1, cudaEventDisableTiming);
    }

    // fork: CSR build runs concurrently with GEMM1
    cudaEventRecord(ev_fork, 0);
    cudaStreamWaitEvent(s_csr, ev_fork, 0);
    cudaMemsetAsync(p_cnt, 0, NN * sizeof(int), s_csr);
    k_deg  <<<(NE + 255) / 256, 256, 0, s_csr>>>(tgt);
    k_alloc<<<(NN + 255) / 256, 256, 0, s_csr>>>();
    k_fill <<<(NE + 255) / 256, 256, 0, s_csr>>>(src, tgt);
    cudaEventRecord(ev_join, s_csr);

    // GEMM1 on main stream (independent of CSR)
    k_gemm_bf<128, 4, 4, 4, float><<<(NN + 255) / 256, 512, smem1>>>(x, W1, h1, 0);

    // join, then chunked pipeline: agg1_c0 ; [agg1_c1 || GEMM2_c0] ; GEMM2_c1 ; agg2
    cudaStreamWaitEvent(0, ev_join, 0);
    k_agg<128, true><<<(CH0_NODES * 32) / 256, 256>>>(h1, a1h, nullptr, b1,
                                                      0, CH0_NODES);
    cudaEventRecord(ev_c0, 0);

    cudaStreamWaitEvent(s_csr, ev_c0, 0);
    k_agg<128, true><<<((NN - CH0_NODES) * 32 + 255) / 256, 256, 0, s_csr>>>(
        h1, a1h, nullptr, b1, CH0_NODES, NN);
    cudaEventRecord(ev_c1, s_csr);

    k_gemm_bf<64, 8, 2, 4, __half><<<CH0_TILES, 512, smem2>>>(a1h, W2, h2, 0);
    cudaStreamWaitEvent(0, ev_c1, 0);
    k_gemm_bf<64, 8, 2, 4, __half><<<(NN + 255) / 256 - CH0_TILES, 512, smem2>>>(
        a1h, W2, h2, CH0_TILES);
    k_agg<64, false><<<(NN * 32 + 255) / 256, 256>>>(h2, nullptr, out, b2, 0, NN);
}